// round 9
// baseline (speedup 1.0000x reference)
#include <cuda_runtime.h>
#include <cuda_bf16.h>
#include <math.h>
#include <stdint.h>

#define D 64
#define N_MAX 327680
#define S_MAX 16384

// ---- scratch ----
__device__ float g_hA  [N_MAX * D];   // final h (written by layer 1)
__device__ float g_hB  [N_MAX * D];   // layer-0 output
__device__ float g_vnW1[S_MAX * D];
__device__ float g_sg  [S_MAX * D];
__device__ float g_sh  [S_MAX * D];
__device__ int   g_last[S_MAX];
__device__ int   g_inedge[N_MAX];
__device__ double g_acc[2];
__device__ __align__(16) uint16_t g_gruBb[256 * 128];   // bf16 gate-interleaved [c=4j+g][k]
__device__ __align__(16) uint16_t g_msgGb[2 * 64 * 64]; // bf16 [layer][col j][k]
__device__ __align__(16) uint16_t g_w2Bb [64 * 64];     // bf16 [j][k]

// ---------------------------------------------------------------- helpers
__device__ __forceinline__ float fsigmoid(float x) {
    float e = __expf(-x);
    float r;
    asm("rcp.approx.f32 %0, %1;" : "=f"(r) : "f"(1.f + e));
    return r;
}
__device__ __forceinline__ float ftanh_(float x) {
    float t;
    asm("tanh.approx.f32 %0, %1;" : "=f"(t) : "f"(x));
    return t;
}
__device__ __forceinline__ uint32_t pbf2(float lo, float hi) {
    uint32_t o;
    asm("cvt.rn.bf16x2.f32 %0, %1, %2;" : "=r"(o) : "f"(hi), "f"(lo));
    return o;
}
__device__ __forceinline__ uint32_t smem_u32(const void* p) {
    return (uint32_t)__cvta_generic_to_shared(p);
}
__device__ __forceinline__ void cp16(uint32_t dst, const void* src) {
    asm volatile("cp.async.cg.shared.global [%0], [%1], 16;" :: "r"(dst), "l"(src));
}
__device__ __forceinline__ void mma_bf16(float d[4], const uint32_t a[4],
                                         uint32_t b0, uint32_t b1)
{
    asm volatile(
        "mma.sync.aligned.m16n8k16.row.col.f32.bf16.bf16.f32 "
        "{%0,%1,%2,%3}, {%4,%5,%6,%7}, {%8,%9}, {%0,%1,%2,%3};"
        : "+f"(d[0]), "+f"(d[1]), "+f"(d[2]), "+f"(d[3])
        : "r"(a[0]), "r"(a[1]), "r"(a[2]), "r"(a[3]), "r"(b0), "r"(b1));
}

// ------------------------------------------------ weight prepack (bf16)
__global__ void prepack_kernel(const float* __restrict__ W_ih,
                               const float* __restrict__ W_hh,
                               const float* __restrict__ ggc,
                               const float* __restrict__ W2)
{
    int idx = blockIdx.x * blockDim.x + threadIdx.x;
    if (idx < 256 * 128) {
        int c = idx >> 7, k = idx & 127;
        int j = c >> 2, g = c & 3;
        float v;
        if (g == 0)      v = (k < 64) ? W_ih[j * 64 + k]         : W_hh[j * 64 + (k - 64)];
        else if (g == 1) v = (k < 64) ? W_ih[(64 + j) * 64 + k]  : W_hh[(64 + j) * 64 + (k - 64)];
        else if (g == 2) v = (k < 64) ? W_ih[(128 + j) * 64 + k] : 0.f;
        else             v = (k < 64) ? 0.f                       : W_hh[(128 + j) * 64 + (k - 64)];
        g_gruBb[idx] = __bfloat16_as_ushort(__float2bfloat16_rn(v));
    } else if (idx < 256 * 128 + 2 * 4096) {
        int t = idx - 256 * 128;
        int layer = t >> 12, r = t & 4095;
        int j = r >> 6, k = r & 63;
        g_msgGb[t] = __bfloat16_as_ushort(__float2bfloat16_rn(ggc[layer * 4096 + k * 64 + j]));
    } else if (idx < 256 * 128 + 2 * 4096 + 4096) {
        int t = idx - (256 * 128 + 2 * 4096);
        g_w2Bb[t] = __bfloat16_as_ushort(__float2bfloat16_rn(W2[t]));
    }
}

// ------------------------------------------------------- init helpers
__global__ void zero_misc_kernel(int S, int N)
{
    int i = blockIdx.x * blockDim.x + threadIdx.x;
    if (i < S * D) g_sg[i] = 0.f;
    if (i < S)     g_last[i] = 0;
    if (i < 2)     g_acc[i] = 0.0;
    if (i < N)     g_inedge[i] = -1;
}
__global__ void build_inedge_kernel(const int* __restrict__ src,
                                    const int* __restrict__ dst, int E)
{
    int e = blockIdx.x * blockDim.x + threadIdx.x;
    if (e < E) g_inedge[dst[e]] = src[e];
}
__global__ void lastmax_kernel(const int* __restrict__ batch, int N)
{
    int idx = blockIdx.x * blockDim.x + threadIdx.x;
    if (idx >= N) return;
    atomicMax(&g_last[batch[idx]], idx);
}

// ============================= fused msg + GRU (bf16 mma, 128-row tiles)
#define AKP 136
#define BKP 136
#define HKP 72
#define GRUF_SMEM ((128 * AKP + 256 * BKP) * 2)

__global__ void __launch_bounds__(256, 2) gru_fused(
    int dir, const float* __restrict__ b_ih, const float* __restrict__ b_hh,
    int nrows, int do_relu, int layer,
    const float* __restrict__ emb, const int* __restrict__ items)
{
    extern __shared__ uint16_t smh[];
    uint16_t* sA = smh;                 // [128][AKP]  k<64: agg, k>=64: h
    uint16_t* sB = smh + 128 * AKP;     // [256][BKP]
    uint16_t* sH = sB;                  // alias [128][HKP]
    uint16_t* sG = sB + 128 * HKP;      // alias [64][HKP]

    const float* hin = dir ? g_hB : g_hA;
    float* hout      = dir ? g_hA : g_hB;

    int tid = threadIdx.x;
    int lane = tid & 31;
    int warp = tid >> 5;
    int lr = lane >> 2, lk = lane & 3;
    int rowBase = blockIdx.x * 128;

    // ---- fills ----
    for (int i = tid; i < 128 * 8; i += 256) {          // h (or emb) -> sA[k>=64]
        int r = i >> 3, seg = (i & 7) * 8;
        int gr = rowBase + r;
        float4 v0 = make_float4(0.f,0.f,0.f,0.f), v1 = v0;
        if (gr < nrows) {
            const float* sp = (layer == 0) ? emb + (size_t)(__ldg(&items[gr]) - 1) * 64
                                           : hin + (size_t)gr * 64;
            v0 = *(const float4*)&sp[seg];
            v1 = *(const float4*)&sp[seg + 4];
        }
        uint32_t* dp = (uint32_t*)&sA[r * AKP + 64 + seg];
        dp[0] = pbf2(v0.x, v0.y); dp[1] = pbf2(v0.z, v0.w);
        dp[2] = pbf2(v1.x, v1.y); dp[3] = pbf2(v1.z, v1.w);
    }
    for (int i = tid; i < 128 * 8; i += 256) {          // h[pred] -> sH
        int r = i >> 3, seg = (i & 7) * 8;
        int gr = rowBase + r;
        int p = (gr < nrows) ? __ldg(&g_inedge[gr]) : -1;
        float4 v0 = make_float4(0.f,0.f,0.f,0.f), v1 = v0;
        if (p >= 0) {
            const float* sp = (layer == 0) ? emb + (size_t)(__ldg(&items[p]) - 1) * 64
                                           : hin + (size_t)p * 64;
            v0 = *(const float4*)&sp[seg];
            v1 = *(const float4*)&sp[seg + 4];
        }
        uint32_t* dp = (uint32_t*)&sH[r * HKP + seg];
        dp[0] = pbf2(v0.x, v0.y); dp[1] = pbf2(v0.z, v0.w);
        dp[2] = pbf2(v1.x, v1.y); dp[3] = pbf2(v1.z, v1.w);
    }
    for (int i = tid; i < 64 * 8; i += 256) {           // msg weights -> sG
        int c = i >> 3, q = (i & 7) * 8;
        cp16(smem_u32(&sG[c * HKP + q]), &g_msgGb[layer * 4096 + c * 64 + q]);
    }
    asm volatile("cp.async.commit_group;");
    for (int i = tid; i < 154 * 16; i += 256) {         // gruB tail (c>=102: clear of sH/sG)
        int c = 102 + (i >> 4), q = (i & 15) * 8;
        cp16(smem_u32(&sB[c * BKP + q]), &g_gruBb[c * 128 + q]);
    }
    asm volatile("cp.async.commit_group;");
    asm volatile("cp.async.wait_group 1;");
    __syncthreads();

    // ---- phase 1: P = sH @ sG  (warp: 16 rows x 64 cols) ----
    {
        int rowW1 = warp * 16;
        float p[8][4];
#pragma unroll
        for (int nt = 0; nt < 8; nt++)
#pragma unroll
            for (int q = 0; q < 4; q++) p[nt][q] = 0.f;
#pragma unroll
        for (int k0 = 0; k0 < 64; k0 += 16) {
            uint32_t a[4];
            a[0] = *(const uint32_t*)&sH[(rowW1 + lr) * HKP + k0 + 2 * lk];
            a[1] = *(const uint32_t*)&sH[(rowW1 + lr + 8) * HKP + k0 + 2 * lk];
            a[2] = *(const uint32_t*)&sH[(rowW1 + lr) * HKP + k0 + 8 + 2 * lk];
            a[3] = *(const uint32_t*)&sH[(rowW1 + lr + 8) * HKP + k0 + 8 + 2 * lk];
#pragma unroll
            for (int nt = 0; nt < 8; nt++) {
                int c = nt * 8 + lr;
                uint32_t b0 = *(const uint32_t*)&sG[c * HKP + k0 + 2 * lk];
                uint32_t b1 = *(const uint32_t*)&sG[c * HKP + k0 + 8 + 2 * lk];
                mma_bf16(p[nt], a, b0, b1);
            }
        }
#pragma unroll
        for (int nt = 0; nt < 8; nt++) {
            int c0 = nt * 8 + 2 * lk;
            *(uint32_t*)&sA[(rowW1 + lr) * AKP + c0]     = pbf2(p[nt][0], p[nt][1]);
            *(uint32_t*)&sA[(rowW1 + lr + 8) * AKP + c0] = pbf2(p[nt][2], p[nt][3]);
        }
    }
    __syncthreads();
    for (int i = tid; i < 102 * 16; i += 256) {         // gruB head (c<102)
        int c = i >> 4, q = (i & 15) * 8;
        cp16(smem_u32(&sB[c * BKP + q]), &g_gruBb[c * 128 + q]);
    }
    asm volatile("cp.async.commit_group;");
    asm volatile("cp.async.wait_group 0;");
    __syncthreads();

    // ---- phase 2 + epilogue: two 64-row passes (warp: 32 rows x 64 cols) ----
    for (int half = 0; half < 2; half++) {
        int rowW = half * 64 + (warp >> 2) * 32;
        int colW = (warp & 3) * 64;
        float acc[2][8][4];
#pragma unroll
        for (int mt = 0; mt < 2; mt++)
#pragma unroll
            for (int nt = 0; nt < 8; nt++)
#pragma unroll
                for (int q = 0; q < 4; q++) acc[mt][nt][q] = 0.f;

#pragma unroll
        for (int k0 = 0; k0 < 128; k0 += 16) {
            uint32_t a[2][4];
#pragma unroll
            for (int mt = 0; mt < 2; mt++) {
                int r = rowW + mt * 16 + lr;
                a[mt][0] = *(const uint32_t*)&sA[r * AKP + k0 + 2 * lk];
                a[mt][1] = *(const uint32_t*)&sA[(r + 8) * AKP + k0 + 2 * lk];
                a[mt][2] = *(const uint32_t*)&sA[r * AKP + k0 + 8 + 2 * lk];
                a[mt][3] = *(const uint32_t*)&sA[(r + 8) * AKP + k0 + 8 + 2 * lk];
            }
#pragma unroll
            for (int nt = 0; nt < 8; nt++) {
                int c = colW + nt * 8 + lr;
                uint32_t b0 = *(const uint32_t*)&sB[c * BKP + k0 + 2 * lk];
                uint32_t b1 = *(const uint32_t*)&sB[c * BKP + k0 + 8 + 2 * lk];
                mma_bf16(acc[0][nt], a[0], b0, b1);
                mma_bf16(acc[1][nt], a[1], b0, b1);
            }
        }

        int base_j = colW >> 2;
        int odd = lk & 1;
#pragma unroll
        for (int mt = 0; mt < 2; mt++) {
            int r0g = rowBase + rowW + 16 * mt + lr;
            int r1g = r0g + 8;
            const float* hop0 = nullptr;
            const float* hop1 = nullptr;
            if (r0g < nrows)
                hop0 = (layer == 0) ? emb + (size_t)(__ldg(&items[r0g]) - 1) * 64
                                    : hin + (size_t)r0g * 64;
            if (r1g < nrows)
                hop1 = (layer == 0) ? emb + (size_t)(__ldg(&items[r1g]) - 1) * 64
                                    : hin + (size_t)r1g * 64;
#pragma unroll
            for (int nt = 0; nt < 8; nt++) {
                int j = base_j + 2 * nt + ((lk >> 1) & 1);
                float s0 = acc[mt][nt][0], s1 = acc[mt][nt][1];
                float s2 = acc[mt][nt][2], s3 = acc[mt][nt][3];
                float e0 = __shfl_xor_sync(0xffffffffu, s0, 1);
                float e1 = __shfl_xor_sync(0xffffffffu, s1, 1);
                float e2 = __shfl_xor_sync(0xffffffffu, s2, 1);
                float e3 = __shfl_xor_sync(0xffffffffu, s3, 1);
                float xr0 = odd ? e0 : s0, xz0 = odd ? e1 : s1;
                float xi0 = odd ? s0 : e0, xn0 = odd ? s1 : e1;
                float xr1 = odd ? e2 : s2, xz1 = odd ? e3 : s3;
                float xi1 = odd ? s2 : e2, xn1 = odd ? s3 : e3;
                float br = __ldg(&b_ih[j])      + __ldg(&b_hh[j]);
                float bz = __ldg(&b_ih[64 + j]) + __ldg(&b_hh[64 + j]);
                float bi = __ldg(&b_ih[128 + j]);
                float bn = __ldg(&b_hh[128 + j]);
                float ho0 = hop0 ? hop0[j] : 0.f;
                float ho1 = hop1 ? hop1[j] : 0.f;
                float rr0 = fsigmoid(xr0 + br), zz0 = fsigmoid(xz0 + bz);
                float nn0 = ftanh_(fmaf(rr0, xn0 + bn, xi0 + bi));
                float v0 = fmaf(zz0, ho0 - nn0, nn0);
                float rr1 = fsigmoid(xr1 + br), zz1 = fsigmoid(xz1 + bz);
                float nn1 = ftanh_(fmaf(rr1, xn1 + bn, xi1 + bi));
                float v1 = fmaf(zz1, ho1 - nn1, nn1);
                if (do_relu) { v0 = fmaxf(v0, 0.f); v1 = fmaxf(v1, 0.f); }
                float w0 = __shfl_xor_sync(0xffffffffu, v0, 2);
                float w1 = __shfl_xor_sync(0xffffffffu, v1, 2);
                if (lk == 0) {
                    if (r0g < nrows) *(float2*)&hout[r0g * 64 + j] = make_float2(v0, w0);
                    if (r1g < nrows) *(float2*)&hout[r1g * 64 + j] = make_float2(v1, w1);
                }
            }
        }
    }
}

// --------------------- vn_mma: [vnW1 | sh_a] = h[last] @ [W1^T | W3a^T]
#define VN_SMEM ((64 * 68 + 64 * 132) * 4)
__global__ void __launch_bounds__(256) vn_mma(
    const float* __restrict__ W1, const float* __restrict__ W3, int S)
{
    extern __shared__ float vnsm[];
    float* sAt = vnsm;             // [k][row] 64x68
    float* sB  = vnsm + 64 * 68;   // [k][col] 64x132

    int tid = threadIdx.x;
    int rowBase = blockIdx.x * 64;

    for (int i = tid; i < 64 * 64; i += 256) {
        int r = i >> 6, k = i & 63;
        int s = rowBase + r;
        float v = 0.f;
        if (s < S) v = g_hA[(size_t)__ldg(&g_last[s]) * 64 + k];
        sAt[k * 68 + r] = v;
    }
    for (int i = tid; i < 64 * 128; i += 256) {
        int c = i >> 6, k = i & 63;
        float v = (c < 64) ? W1[c * 64 + k] : W3[(c - 64) * 128 + k];
        sB[k * 132 + c] = v;
    }
    __syncthreads();

    int r0 = (tid >> 4) * 4, c0 = (tid & 15) * 8;
    float acc[4][8] = {};
#pragma unroll
    for (int k = 0; k < 64; k++) {
        float4 a = *(const float4*)&sAt[k * 68 + r0];
        float4 bA = *(const float4*)&sB[k * 132 + c0];
        float4 bB = *(const float4*)&sB[k * 132 + c0 + 4];
        float av[4] = {a.x, a.y, a.z, a.w};
        float bv[8] = {bA.x, bA.y, bA.z, bA.w, bB.x, bB.y, bB.z, bB.w};
#pragma unroll
        for (int i = 0; i < 4; i++)
#pragma unroll
            for (int j = 0; j < 8; j++)
                acc[i][j] = fmaf(av[i], bv[j], acc[i][j]);
    }

#pragma unroll
    for (int i = 0; i < 4; i++) {
        int s = rowBase + r0 + i;
        if (s >= S) continue;
        float* outp = (c0 < 64) ? &g_vnW1[s * 64 + c0] : &g_sh[s * 64 + (c0 - 64)];
        *(float4*)outp       = make_float4(acc[i][0], acc[i][1], acc[i][2], acc[i][3]);
        *(float4*)(outp + 4) = make_float4(acc[i][4], acc[i][5], acc[i][6], acc[i][7]);
    }
}

// ------------------------- bf16 mma: hW2 + register gate epilogue
#define W2_SMEM ((128 * 72 + 64 * 72) * 2)
__global__ void __launch_bounds__(256) w2gate_mma(
    const int* __restrict__ batch,
    const float* __restrict__ bb1, const float* __restrict__ bb2,
    const float* __restrict__ qw, const float* __restrict__ qb,
    int nrows)
{
    extern __shared__ uint16_t smw[];
    uint16_t* sA = smw;               // [128][72]
    uint16_t* sB = smw + 128 * 72;    // [64][72]

    int tid = threadIdx.x;
    int lane = tid & 31;
    int warp = tid >> 5;
    int lr = lane >> 2, lk = lane & 3;
    int rowBase = blockIdx.x * 128;

    for (int i = tid; i < 128 * 8; i += 256) {
        int r = i >> 3, seg = (i & 7) * 8;
        int gr = rowBase + r;
        float4 v0 = make_float4(0.f,0.f,0.f,0.f), v1 = v0;
        if (gr < nrows) {
            v0 = *(const float4*)&g_hA[gr * 64 + seg];
            v1 = *(const float4*)&g_hA[gr * 64 + seg + 4];
        }
        uint32_t* dp = (uint32_t*)&sA[r * 72 + seg];
        dp[0] = pbf2(v0.x, v0.y); dp[1] = pbf2(v0.z, v0.w);
        dp[2] = pbf2(v1.x, v1.y); dp[3] = pbf2(v1.z, v1.w);
    }
    for (int i = tid; i < 64 * 8; i += 256) {
        int c = i >> 3, q = (i & 7) * 8;
        cp16(smem_u32(&sB[c * 72 + q]), &g_w2Bb[c * 64 + q]);
    }
    asm volatile("cp.async.commit_group;");
    asm volatile("cp.async.wait_group 0;");
    __syncthreads();

    int rowW = warp * 16;
    float acc[8][4];
#pragma unroll
    for (int nt = 0; nt < 8; nt++)
#pragma unroll
        for (int q = 0; q < 4; q++) acc[nt][q] = 0.f;

#pragma unroll
    for (int k0 = 0; k0 < 64; k0 += 16) {
        uint32_t a[4];
        a[0] = *(const uint32_t*)&sA[(rowW + lr) * 72 + k0 + 2 * lk];
        a[1] = *(const uint32_t*)&sA[(rowW + lr + 8) * 72 + k0 + 2 * lk];
        a[2] = *(const uint32_t*)&sA[(rowW + lr) * 72 + k0 + 8 + 2 * lk];
        a[3] = *(const uint32_t*)&sA[(rowW + lr + 8) * 72 + k0 + 8 + 2 * lk];
#pragma unroll
        for (int nt = 0; nt < 8; nt++) {
            int c = nt * 8 + lr;
            uint32_t b0 = *(const uint32_t*)&sB[c * 72 + k0 + 2 * lk];
            uint32_t b1 = *(const uint32_t*)&sB[c * 72 + k0 + 8 + 2 * lk];
            mma_bf16(acc[nt], a, b0, b1);
        }
    }

    // register epilogue
    int r0g = rowBase + rowW + lr;
    int r1g = r0g + 8;
    int bs0 = (r0g < nrows) ? __ldg(&batch[r0g]) : 0;
    int bs1 = (r1g < nrows) ? __ldg(&batch[r1g]) : 0;
    float al0 = 0.f, al1 = 0.f;
#pragma unroll
    for (int nt = 0; nt < 8; nt++) {
#pragma unroll
        for (int q = 0; q < 2; q++) {
            int c = nt * 8 + 2 * lk + q;
            float bias = __ldg(&bb1[c]) + __ldg(&bb2[c]);
            float qv = __ldg(&qw[c]);
            float x0 = acc[nt][q]     + g_vnW1[bs0 * 64 + c] + bias;
            float x1 = acc[nt][2 + q] + g_vnW1[bs1 * 64 + c] + bias;
            al0 = fmaf(fsigmoid(x0), qv, al0);
            al1 = fmaf(fsigmoid(x1), qv, al1);
        }
    }
    al0 += __shfl_xor_sync(0xffffffffu, al0, 1);
    al0 += __shfl_xor_sync(0xffffffffu, al0, 2);
    al1 += __shfl_xor_sync(0xffffffffu, al1, 1);
    al1 += __shfl_xor_sync(0xffffffffu, al1, 2);
    float qbv = __ldg(&qb[0]);
    al0 += qbv; al1 += qbv;
#pragma unroll
    for (int nt = 0; nt < 8; nt++) {
#pragma unroll
        for (int q = 0; q < 2; q++) {
            int c = nt * 8 + 2 * lk + q;
            if (r0g < nrows) atomicAdd(&g_sg[bs0 * 64 + c], al0 * g_hA[r0g * 64 + c]);
            if (r1g < nrows) atomicAdd(&g_sg[bs1 * 64 + c], al1 * g_hA[r1g * 64 + c]);
        }
    }
}

// --------------------- final accum: g_sh += g_sg @ W3b^T + b3
__global__ void __launch_bounds__(256) shb_gemm(
    const float* __restrict__ W3, const float* __restrict__ b3, int S)
{
    __shared__ float sAt[64][68];
    __shared__ float sB [64][68];
    int tid = threadIdx.x;
    int rowBase = blockIdx.x * 64;

    for (int i = tid; i < 64 * 64; i += 256) {
        int r = i >> 6, k = i & 63;
        int s = rowBase + r;
        sAt[k][r] = (s < S) ? g_sg[s * 64 + k] : 0.f;
    }
    for (int i = tid; i < 64 * 64; i += 256) {
        int j = i >> 6, k = i & 63;
        sB[k][j] = W3[j * 128 + 64 + k];
    }
    __syncthreads();

    int r0 = (tid >> 4) * 4, c0 = (tid & 15) * 4;
    float acc[4][4] = {};
#pragma unroll
    for (int k = 0; k < 64; k++) {
        float4 a = *(const float4*)&sAt[k][r0];
        float4 b = *(const float4*)&sB[k][c0];
        float av[4] = {a.x, a.y, a.z, a.w};
        float bv[4] = {b.x, b.y, b.z, b.w};
#pragma unroll
        for (int i = 0; i < 4; i++)
#pragma unroll
            for (int j = 0; j < 4; j++)
                acc[i][j] = fmaf(av[i], bv[j], acc[i][j]);
    }

    float4 bb = make_float4(b3[c0], b3[c0+1], b3[c0+2], b3[c0+3]);
#pragma unroll
    for (int i = 0; i < 4; i++) {
        int s = rowBase + r0 + i;
        if (s < S) {
            float* cp = &g_sh[s * 64 + c0];
            float4 p = *(const float4*)cp;
            *(float4*)cp = make_float4(acc[i][0] + bb.x + p.x, acc[i][1] + bb.y + p.y,
                                       acc[i][2] + bb.z + p.z, acc[i][3] + bb.w + p.w);
        }
    }
}

// ------------------------------------------------------------ BPR loss
__global__ void loss_kernel(const float* __restrict__ item_emb,
                            const int* __restrict__ pos, const int* __restrict__ neg,
                            int S)
{
    int gidx = blockIdx.x * blockDim.x + threadIdx.x;
    int s = gidx >> 5;
    if (s >= S) return;
    int lane = gidx & 31;
    int ip = pos[s], in2 = neg[s];
    float pp = 0.f, np = 0.f, rg = 0.f;
#pragma unroll
    for (int t = 0; t < 2; t++) {
        int j = lane + t * 32;
        float sv = g_sh[s * 64 + j];
        float pe = item_emb[ip * 64 + j];
        float ne = item_emb[in2 * 64 + j];
        pp = fmaf(sv, pe, pp);
        np = fmaf(sv, ne, np);
        rg += sv * sv + pe * pe + ne * ne;
    }
#pragma unroll
    for (int o = 16; o; o >>= 1) {
        pp += __shfl_xor_sync(0xffffffffu, pp, o);
        np += __shfl_xor_sync(0xffffffffu, np, o);
        rg += __shfl_xor_sync(0xffffffffu, rg, o);
    }
    if (lane == 0) {
        float x = pp - np;
        float lsm = (x > 0.f) ? log1pf(expf(-x)) : (-x + log1pf(expf(x)));
        atomicAdd(&g_acc[0], (double)lsm);
        atomicAdd(&g_acc[1], (double)rg);
    }
}

__global__ void finalize_kernel(float* out, int out_size)
{
    double loss = g_acc[0];
    double nr = g_acc[1] * 1e-5;
    float t = (float)(loss + nr), l = (float)loss, r = (float)nr;
    if (out_size > 0) out[0] = t;
    if (out_size > 1) out[1] = l;
    if (out_size > 2) out[2] = r;
    if (out_size > 3) out[3] = r;
    if (out_size > 4) out[4] = r;
}

// ---------------------------------------------------------------- host
extern "C" void kernel_launch(void* const* d_in, const int* in_sizes, int n_in,
                              void* d_out, int out_size)
{
    const float* item_emb = (const float*)d_in[0];
    const float* ggc      = (const float*)d_in[1];
    const float* W_ih     = (const float*)d_in[2];
    const float* b_ih     = (const float*)d_in[3];
    const float* W_hh     = (const float*)d_in[4];
    const float* b_hh     = (const float*)d_in[5];
    const float* W1       = (const float*)d_in[6];
    const float* b1       = (const float*)d_in[7];
    const float* W2       = (const float*)d_in[8];
    const float* b2       = (const float*)d_in[9];
    const float* qw       = (const float*)d_in[10];
    const float* qb       = (const float*)d_in[11];
    const float* W3       = (const float*)d_in[12];
    const float* b3       = (const float*)d_in[13];
    const int* node_items = (const int*)d_in[14];
    const int* edge_index = (const int*)d_in[15];
    const int* batch      = (const int*)d_in[16];
    const int* pos        = (const int*)d_in[17];
    const int* neg        = (const int*)d_in[18];

    int N = in_sizes[14];
    int E = in_sizes[15] / 2;
    int S = in_sizes[17];
    float* out = (float*)d_out;

    cudaFuncSetAttribute(gru_fused,  cudaFuncAttributeMaxDynamicSharedMemorySize, GRUF_SMEM);
    cudaFuncSetAttribute(w2gate_mma, cudaFuncAttributeMaxDynamicSharedMemorySize, W2_SMEM);
    cudaFuncSetAttribute(vn_mma,     cudaFuncAttributeMaxDynamicSharedMemorySize, VN_SMEM);

    const int* src = edge_index;
    const int* dst = edge_index + E;
    int gTiles = (N + 127) / 128;
    int initCnt = (N > S * D) ? N : S * D;

    prepack_kernel<<<(256 * 128 + 3 * 4096 + 255) / 256, 256>>>(W_ih, W_hh, ggc, W2);
    zero_misc_kernel<<<(initCnt + 255) / 256, 256>>>(S, N);
    build_inedge_kernel<<<(E + 255) / 256, 256>>>(src, dst, E);
    lastmax_kernel<<<(N + 255) / 256, 256>>>(batch, N);

    // layer 0: emb -> g_hB ; layer 1: g_hB -> g_hA (+relu)
    gru_fused<<<gTiles, 256, GRUF_SMEM>>>(0, b_ih, b_hh, N, 0, 0, item_emb, node_items);
    gru_fused<<<gTiles, 256, GRUF_SMEM>>>(1, b_ih, b_hh, N, 1, 1, item_emb, node_items);

    vn_mma<<<(S + 63) / 64, 256, VN_SMEM>>>(W1, W3, S);
    w2gate_mma<<<gTiles, 256, W2_SMEM>>>(batch, b1, b2, qw, qb, N);
    shb_gemm<<<(S + 63) / 64, 256>>>(W3, b3, S);

    loss_kernel<<<(S * 32 + 255) / 256, 256>>>(item_emb, pos, neg, S);
    finalize_kernel<<<1, 1>>>(out, out_size);
}

// round 11
// speedup vs baseline: 1.0815x; 1.0815x over previous
#include <cuda_runtime.h>
#include <cuda_bf16.h>
#include <math.h>
#include <stdint.h>

#define D 64
#define N_MAX 327680
#define S_MAX 16384

// ---- scratch ----
__device__ float g_hA  [N_MAX * D];   // final h after both layers (+relu)
__device__ float g_vnW1[S_MAX * D];
__device__ float g_sg  [S_MAX * D];
__device__ float g_sh  [S_MAX * D];
__device__ int   g_last[S_MAX];
__device__ int   g_inedge[N_MAX];
__device__ double g_acc[2];
__device__ __align__(16) uint16_t g_gruBb[256 * 128];   // bf16 gate-interleaved [c=4j+g][k]
__device__ __align__(16) uint16_t g_msgGb[2 * 64 * 64]; // bf16 [layer][col j][k]
__device__ __align__(16) uint16_t g_w2Bb [64 * 64];     // bf16 [j][k]

// ---------------------------------------------------------------- helpers
__device__ __forceinline__ float fsigmoid(float x) {
    float e = __expf(-x);
    float r;
    asm("rcp.approx.f32 %0, %1;" : "=f"(r) : "f"(1.f + e));
    return r;
}
__device__ __forceinline__ float ftanh_(float x) {
    float t;
    asm("tanh.approx.f32 %0, %1;" : "=f"(t) : "f"(x));
    return t;
}
__device__ __forceinline__ uint32_t pbf2(float lo, float hi) {
    uint32_t o;
    asm("cvt.rn.bf16x2.f32 %0, %1, %2;" : "=r"(o) : "f"(hi), "f"(lo));
    return o;
}
__device__ __forceinline__ float bf2f(uint16_t u) {
    return __uint_as_float(((uint32_t)u) << 16);
}
__device__ __forceinline__ uint32_t smem_u32(const void* p) {
    return (uint32_t)__cvta_generic_to_shared(p);
}
__device__ __forceinline__ void cp16(uint32_t dst, const void* src) {
    asm volatile("cp.async.cg.shared.global [%0], [%1], 16;" :: "r"(dst), "l"(src));
}
__device__ __forceinline__ void mma_bf16(float d[4], const uint32_t a[4],
                                         uint32_t b0, uint32_t b1)
{
    asm volatile(
        "mma.sync.aligned.m16n8k16.row.col.f32.bf16.bf16.f32 "
        "{%0,%1,%2,%3}, {%4,%5,%6,%7}, {%8,%9}, {%0,%1,%2,%3};"
        : "+f"(d[0]), "+f"(d[1]), "+f"(d[2]), "+f"(d[3])
        : "r"(a[0]), "r"(a[1]), "r"(a[2]), "r"(a[3]), "r"(b0), "r"(b1));
}

// ------------------------------------- merged init: prepack + zero + last
__global__ void init_all(const float* __restrict__ W_ih, const float* __restrict__ W_hh,
                         const float* __restrict__ ggc, const float* __restrict__ W2,
                         const int* __restrict__ batch, int S, int N)
{
    int i = blockIdx.x * blockDim.x + threadIdx.x;
    if (i < 256 * 128) {
        int c = i >> 7, k = i & 127;
        int j = c >> 2, g = c & 3;
        float v;
        if (g == 0)      v = (k < 64) ? W_ih[j * 64 + k]         : W_hh[j * 64 + (k - 64)];
        else if (g == 1) v = (k < 64) ? W_ih[(64 + j) * 64 + k]  : W_hh[(64 + j) * 64 + (k - 64)];
        else if (g == 2) v = (k < 64) ? W_ih[(128 + j) * 64 + k] : 0.f;
        else             v = (k < 64) ? 0.f                       : W_hh[(128 + j) * 64 + (k - 64)];
        g_gruBb[i] = __bfloat16_as_ushort(__float2bfloat16_rn(v));
    } else if (i < 256 * 128 + 2 * 4096) {
        int t = i - 256 * 128;
        int layer = t >> 12, r = t & 4095;
        int j = r >> 6, k = r & 63;
        g_msgGb[t] = __bfloat16_as_ushort(__float2bfloat16_rn(ggc[layer * 4096 + k * 64 + j]));
    } else if (i < 256 * 128 + 2 * 4096 + 4096) {
        int t = i - (256 * 128 + 2 * 4096);
        g_w2Bb[t] = __bfloat16_as_ushort(__float2bfloat16_rn(W2[t]));
    }
    if (i < S * 64) g_sg[i] = 0.f;
    if (i < 2)      g_acc[i] = 0.0;
    if (i < N) {
        g_inedge[i] = -1;
        int b = __ldg(&batch[i]);
        if (i == N - 1 || __ldg(&batch[i + 1]) != b) g_last[b] = i;   // batch sorted
    }
}
__global__ void build_inedge_kernel(const int* __restrict__ src,
                                    const int* __restrict__ dst, int E)
{
    int e = blockIdx.x * blockDim.x + threadIdx.x;
    if (e < E) g_inedge[dst[e]] = src[e];
}

// ================== single-kernel 2-layer GGC+GRU (64-row tiles, 16 halo)
// smem (halfwords): sAgg[80][72] | sX0[80][72] | sX1[80][72] | sG[64][72] | sB[256][136]
#define XP 72
#define BKP 136
#define OF_AGG 0
#define OF_X0  5760
#define OF_X1  11520
#define OF_G   17280
#define OF_B   21888
#define GNN_SMEM ((21888 + 256 * 136) * 2)

// phase-1: P = src80 @ sG, rowblock rb (16 rows), N=64, K=64, in-place into dst
__device__ __forceinline__ void p1_tile(uint16_t* sSrc, uint16_t* sDst,
                                        const uint16_t* sG, int rb, int lr, int lk)
{
    int r0 = rb * 16 + lr;
    float p[8][4];
#pragma unroll
    for (int nt = 0; nt < 8; nt++)
#pragma unroll
        for (int q = 0; q < 4; q++) p[nt][q] = 0.f;
#pragma unroll
    for (int k0 = 0; k0 < 64; k0 += 16) {
        uint32_t a[4];
        a[0] = *(const uint32_t*)&sSrc[r0 * XP + k0 + 2 * lk];
        a[1] = *(const uint32_t*)&sSrc[(r0 + 8) * XP + k0 + 2 * lk];
        a[2] = *(const uint32_t*)&sSrc[r0 * XP + k0 + 8 + 2 * lk];
        a[3] = *(const uint32_t*)&sSrc[(r0 + 8) * XP + k0 + 8 + 2 * lk];
#pragma unroll
        for (int nt = 0; nt < 8; nt++) {
            int c = nt * 8 + lr;
            uint32_t b0 = *(const uint32_t*)&sG[c * XP + k0 + 2 * lk];
            uint32_t b1 = *(const uint32_t*)&sG[c * XP + k0 + 8 + 2 * lk];
            mma_bf16(p[nt], a, b0, b1);
        }
    }
#pragma unroll
    for (int nt = 0; nt < 8; nt++) {
        int c0 = nt * 8 + 2 * lk;
        *(uint32_t*)&sDst[r0 * XP + c0]       = pbf2(p[nt][0], p[nt][1]);
        *(uint32_t*)&sDst[(r0 + 8) * XP + c0] = pbf2(p[nt][2], p[nt][3]);
    }
}

__global__ void __launch_bounds__(256, 2) gnn2(
    const float* __restrict__ b_ih, const float* __restrict__ b_hh,
    int nrows, const float* __restrict__ emb, const int* __restrict__ items)
{
    extern __shared__ uint16_t sm[];
    uint16_t* sAgg = sm + OF_AGG;
    uint16_t* sX0  = sm + OF_X0;
    uint16_t* sX1  = sm + OF_X1;
    uint16_t* sG   = sm + OF_G;
    uint16_t* sB   = sm + OF_B;

    int tid = threadIdx.x, lane = tid & 31, warp = tid >> 5;
    int lr = lane >> 2, lk = lane & 3;
    int rowBase = blockIdx.x * 64;
    int gr0base = rowBase - 16;

    // async weight loads: sG(layer0) group A; gruB group B
    for (int i = tid; i < 64 * 8; i += 256) {
        int c = i >> 3, q = (i & 7) * 8;
        cp16(smem_u32(&sG[c * XP + q]), &g_msgGb[c * 64 + q]);
    }
    asm volatile("cp.async.commit_group;");
    for (int i = tid; i < 256 * 16; i += 256) {
        int c = i >> 4, q = (i & 15) * 8;
        cp16(smem_u32(&sB[c * BKP + q]), &g_gruBb[c * 128 + q]);
    }
    asm volatile("cp.async.commit_group;");

    // fills: sX0 = emb[items[gr]] ; sAgg = emb[items[pred]]
    for (int i = tid; i < 80 * 8; i += 256) {
        int rl = i >> 3, seg = (i & 7) * 8;
        int gr = gr0base + rl;
        float4 v0 = make_float4(0.f,0.f,0.f,0.f), v1 = v0;
        if (gr >= 0 && gr < nrows) {
            const float* sp = emb + (size_t)(__ldg(&items[gr]) - 1) * 64;
            v0 = *(const float4*)&sp[seg];
            v1 = *(const float4*)&sp[seg + 4];
        }
        uint32_t* dp = (uint32_t*)&sX0[rl * XP + seg];
        dp[0] = pbf2(v0.x, v0.y); dp[1] = pbf2(v0.z, v0.w);
        dp[2] = pbf2(v1.x, v1.y); dp[3] = pbf2(v1.z, v1.w);
    }
    for (int i = tid; i < 80 * 8; i += 256) {
        int rl = i >> 3, seg = (i & 7) * 8;
        int gr = gr0base + rl;
        int p = (gr >= 0 && gr < nrows) ? __ldg(&g_inedge[gr]) : -1;
        float4 v0 = make_float4(0.f,0.f,0.f,0.f), v1 = v0;
        if (p >= 0) {
            const float* sp = emb + (size_t)(__ldg(&items[p]) - 1) * 64;
            v0 = *(const float4*)&sp[seg];
            v1 = *(const float4*)&sp[seg + 4];
        }
        uint32_t* dp = (uint32_t*)&sAgg[rl * XP + seg];
        dp[0] = pbf2(v0.x, v0.y); dp[1] = pbf2(v0.z, v0.w);
        dp[2] = pbf2(v1.x, v1.y); dp[3] = pbf2(v1.z, v1.w);
    }
    asm volatile("cp.async.wait_group 1;");   // sG ready
    __syncthreads();

    // ---- layer 0 phase 1: P0 = sAgg @ sG (in place), rowblocks 0..4 ----
    if (warp < 5) p1_tile(sAgg, sAgg, sG, warp, lr, lk);
    asm volatile("cp.async.wait_group 0;");   // gruB ready
    __syncthreads();

    // ---- layer 0 phase 2 + GRU epilogue -> sX1 (bf16 h0) ----
    for (int t = warp; t < 20; t += 8) {
        int rb = t >> 2, cb = t & 3;
        int r0 = rb * 16 + lr;
        int colW = cb * 64;
        float acc[8][4];
#pragma unroll
        for (int nt = 0; nt < 8; nt++)
#pragma unroll
            for (int q = 0; q < 4; q++) acc[nt][q] = 0.f;
#pragma unroll
        for (int kk = 0; kk < 8; kk++) {
            int k0 = kk * 16;
            const uint16_t* ab = (k0 < 64) ? sAgg : sX0;
            int kc = (k0 < 64) ? k0 : k0 - 64;
            uint32_t a[4];
            a[0] = *(const uint32_t*)&ab[r0 * XP + kc + 2 * lk];
            a[1] = *(const uint32_t*)&ab[(r0 + 8) * XP + kc + 2 * lk];
            a[2] = *(const uint32_t*)&ab[r0 * XP + kc + 8 + 2 * lk];
            a[3] = *(const uint32_t*)&ab[(r0 + 8) * XP + kc + 8 + 2 * lk];
#pragma unroll
            for (int nt = 0; nt < 8; nt++) {
                int c = colW + nt * 8 + lr;
                uint32_t b0 = *(const uint32_t*)&sB[c * BKP + k0 + 2 * lk];
                uint32_t b1 = *(const uint32_t*)&sB[c * BKP + k0 + 8 + 2 * lk];
                mma_bf16(acc[nt], a, b0, b1);
            }
        }
        // epilogue (h_old = exact fp32 emb, no relu, write bf16 h0 -> sX1)
        int base_j = colW >> 2;
        int odd = lk & 1;
        int rg0 = gr0base + r0, rg1 = rg0 + 8;
        const float* hop0 = (rg0 >= 0 && rg0 < nrows)
                          ? emb + (size_t)(__ldg(&items[rg0]) - 1) * 64 : nullptr;
        const float* hop1 = (rg1 >= 0 && rg1 < nrows)
                          ? emb + (size_t)(__ldg(&items[rg1]) - 1) * 64 : nullptr;
#pragma unroll
        for (int nt = 0; nt < 8; nt++) {
            int j = base_j + 2 * nt + ((lk >> 1) & 1);
            float s0 = acc[nt][0], s1 = acc[nt][1], s2 = acc[nt][2], s3 = acc[nt][3];
            float e0 = __shfl_xor_sync(0xffffffffu, s0, 1);
            float e1 = __shfl_xor_sync(0xffffffffu, s1, 1);
            float e2 = __shfl_xor_sync(0xffffffffu, s2, 1);
            float e3 = __shfl_xor_sync(0xffffffffu, s3, 1);
            float xr0 = odd ? e0 : s0, xz0 = odd ? e1 : s1;
            float xi0 = odd ? s0 : e0, xn0 = odd ? s1 : e1;
            float xr1 = odd ? e2 : s2, xz1 = odd ? e3 : s3;
            float xi1 = odd ? s2 : e2, xn1 = odd ? s3 : e3;
            float br = __ldg(&b_ih[j])      + __ldg(&b_hh[j]);
            float bz = __ldg(&b_ih[64 + j]) + __ldg(&b_hh[64 + j]);
            float bi = __ldg(&b_ih[128 + j]);
            float bn = __ldg(&b_hh[128 + j]);
            float ho0 = hop0 ? hop0[j] : 0.f;
            float ho1 = hop1 ? hop1[j] : 0.f;
            float rr0 = fsigmoid(xr0 + br), zz0 = fsigmoid(xz0 + bz);
            float nn0 = ftanh_(fmaf(rr0, xn0 + bn, xi0 + bi));
            float v0 = fmaf(zz0, ho0 - nn0, nn0);
            float rr1 = fsigmoid(xr1 + br), zz1 = fsigmoid(xz1 + bz);
            float nn1 = ftanh_(fmaf(rr1, xn1 + bn, xi1 + bi));
            float v1 = fmaf(zz1, ho1 - nn1, nn1);
            float w0 = __shfl_xor_sync(0xffffffffu, v0, 2);
            float w1 = __shfl_xor_sync(0xffffffffu, v1, 2);
            if (lk == 0) {
                *(uint32_t*)&sX1[r0 * XP + j]       = pbf2(v0, w0);
                *(uint32_t*)&sX1[(r0 + 8) * XP + j] = pbf2(v1, w1);
            }
        }
    }
    __syncthreads();

    // reload sG (layer 1) + pred-copy h0 -> sAgg (root-masked, shift -1 row)
    for (int i = tid; i < 64 * 8; i += 256) {
        int c = i >> 3, q = (i & 7) * 8;
        cp16(smem_u32(&sG[c * XP + q]), &g_msgGb[4096 + c * 64 + q]);
    }
    asm volatile("cp.async.commit_group;");
    for (int i = tid; i < 64 * 8; i += 256) {
        int rl = 16 + (i >> 3), q = (i & 7) * 8;
        int gr = gr0base + rl;
        int p = (gr < nrows) ? __ldg(&g_inedge[gr]) : -1;
        uint4 z = make_uint4(0u, 0u, 0u, 0u);
        uint4 v = (p >= 0) ? *(const uint4*)&sX1[(rl - 1) * XP + q] : z;
        *(uint4*)&sAgg[rl * XP + q] = v;
    }
    asm volatile("cp.async.wait_group 0;");
    __syncthreads();

    // ---- layer 1 phase 1: P1 = sAgg @ sG1 (in place), rowblocks 1..4 ----
    if (warp < 4) p1_tile(sAgg, sAgg, sG, warp + 1, lr, lk);
    __syncthreads();

    // ---- layer 1 phase 2 + GRU epilogue (+relu) -> g_hA ----
    for (int t = warp; t < 16; t += 8) {
        int rb = 1 + (t >> 2), cb = t & 3;
        int r0 = rb * 16 + lr;
        int colW = cb * 64;
        float acc[8][4];
#pragma unroll
        for (int nt = 0; nt < 8; nt++)
#pragma unroll
            for (int q = 0; q < 4; q++) acc[nt][q] = 0.f;
#pragma unroll
        for (int kk = 0; kk < 8; kk++) {
            int k0 = kk * 16;
            const uint16_t* ab = (k0 < 64) ? sAgg : sX1;
            int kc = (k0 < 64) ? k0 : k0 - 64;
            uint32_t a[4];
            a[0] = *(const uint32_t*)&ab[r0 * XP + kc + 2 * lk];
            a[1] = *(const uint32_t*)&ab[(r0 + 8) * XP + kc + 2 * lk];
            a[2] = *(const uint32_t*)&ab[r0 * XP + kc + 8 + 2 * lk];
            a[3] = *(const uint32_t*)&ab[(r0 + 8) * XP + kc + 8 + 2 * lk];
#pragma unroll
            for (int nt = 0; nt < 8; nt++) {
                int c = colW + nt * 8 + lr;
                uint32_t b0 = *(const uint32_t*)&sB[c * BKP + k0 + 2 * lk];
                uint32_t b1 = *(const uint32_t*)&sB[c * BKP + k0 + 8 + 2 * lk];
                mma_bf16(acc[nt], a, b0, b1);
            }
        }
        int base_j = colW >> 2;
        int odd = lk & 1;
        int rg0 = gr0base + r0, rg1 = rg0 + 8;
#pragma unroll
        for (int nt = 0; nt < 8; nt++) {
            int j = base_j + 2 * nt + ((lk >> 1) & 1);
            float s0 = acc[nt][0], s1 = acc[nt][1], s2 = acc[nt][2], s3 = acc[nt][3];
            float e0 = __shfl_xor_sync(0xffffffffu, s0, 1);
            float e1 = __shfl_xor_sync(0xffffffffu, s1, 1);
            float e2 = __shfl_xor_sync(0xffffffffu, s2, 1);
            float e3 = __shfl_xor_sync(0xffffffffu, s3, 1);
            float xr0 = odd ? e0 : s0, xz0 = odd ? e1 : s1;
            float xi0 = odd ? s0 : e0, xn0 = odd ? s1 : e1;
            float xr1 = odd ? e2 : s2, xz1 = odd ? e3 : s3;
            float xi1 = odd ? s2 : e2, xn1 = odd ? s3 : e3;
            float br = __ldg(&b_ih[j])      + __ldg(&b_hh[j]);
            float bz = __ldg(&b_ih[64 + j]) + __ldg(&b_hh[64 + j]);
            float bi = __ldg(&b_ih[128 + j]);
            float bn = __ldg(&b_hh[128 + j]);
            float ho0 = bf2f(sX1[r0 * XP + j]);        // bf16 h0
            float ho1 = bf2f(sX1[(r0 + 8) * XP + j]);
            float rr0 = fsigmoid(xr0 + br), zz0 = fsigmoid(xz0 + bz);
            float nn0 = ftanh_(fmaf(rr0, xn0 + bn, xi0 + bi));
            float v0 = fmaxf(fmaf(zz0, ho0 - nn0, nn0), 0.f);
            float rr1 = fsigmoid(xr1 + br), zz1 = fsigmoid(xz1 + bz);
            float nn1 = ftanh_(fmaf(rr1, xn1 + bn, xi1 + bi));
            float v1 = fmaxf(fmaf(zz1, ho1 - nn1, nn1), 0.f);
            float w0 = __shfl_xor_sync(0xffffffffu, v0, 2);
            float w1 = __shfl_xor_sync(0xffffffffu, v1, 2);
            if (lk == 0) {
                if (rg0 < nrows) *(float2*)&g_hA[rg0 * 64 + j] = make_float2(v0, w0);
                if (rg1 < nrows) *(float2*)&g_hA[rg1 * 64 + j] = make_float2(v1, w1);
            }
        }
    }
}

// --------------------- vn_mma: [vnW1 | sh_a] = h[last] @ [W1^T | W3a^T]
#define VN_SMEM ((64 * 68 + 64 * 132) * 4)
__global__ void __launch_bounds__(256) vn_mma(
    const float* __restrict__ W1, const float* __restrict__ W3, int S)
{
    extern __shared__ float vnsm[];
    float* sAt = vnsm;             // [k][row] 64x68
    float* sB  = vnsm + 64 * 68;   // [k][col] 64x132

    int tid = threadIdx.x;
    int rowBase = blockIdx.x * 64;

    for (int i = tid; i < 64 * 64; i += 256) {
        int r = i >> 6, k = i & 63;
        int s = rowBase + r;
        float v = 0.f;
        if (s < S) v = g_hA[(size_t)__ldg(&g_last[s]) * 64 + k];
        sAt[k * 68 + r] = v;
    }
    for (int i = tid; i < 64 * 128; i += 256) {
        int c = i >> 6, k = i & 63;
        float v = (c < 64) ? W1[c * 64 + k] : W3[(c - 64) * 128 + k];
        sB[k * 132 + c] = v;
    }
    __syncthreads();

    int r0 = (tid >> 4) * 4, c0 = (tid & 15) * 8;
    float acc[4][8] = {};
#pragma unroll
    for (int k = 0; k < 64; k++) {
        float4 a = *(const float4*)&sAt[k * 68 + r0];
        float4 bA = *(const float4*)&sB[k * 132 + c0];
        float4 bB = *(const float4*)&sB[k * 132 + c0 + 4];
        float av[4] = {a.x, a.y, a.z, a.w};
        float bv[8] = {bA.x, bA.y, bA.z, bA.w, bB.x, bB.y, bB.z, bB.w};
#pragma unroll
        for (int i = 0; i < 4; i++)
#pragma unroll
            for (int j = 0; j < 8; j++)
                acc[i][j] = fmaf(av[i], bv[j], acc[i][j]);
    }

#pragma unroll
    for (int i = 0; i < 4; i++) {
        int s = rowBase + r0 + i;
        if (s >= S) continue;
        float* outp = (c0 < 64) ? &g_vnW1[s * 64 + c0] : &g_sh[s * 64 + (c0 - 64)];
        *(float4*)outp       = make_float4(acc[i][0], acc[i][1], acc[i][2], acc[i][3]);
        *(float4*)(outp + 4) = make_float4(acc[i][4], acc[i][5], acc[i][6], acc[i][7]);
    }
}

// ------------------------- bf16 mma: hW2 + register gate epilogue
#define W2_SMEM ((128 * 72 + 64 * 72) * 2)
__global__ void __launch_bounds__(256) w2gate_mma(
    const int* __restrict__ batch,
    const float* __restrict__ bb1, const float* __restrict__ bb2,
    const float* __restrict__ qw, const float* __restrict__ qb,
    int nrows)
{
    extern __shared__ uint16_t smw[];
    uint16_t* sA = smw;               // [128][72]
    uint16_t* sB = smw + 128 * 72;    // [64][72]

    int tid = threadIdx.x;
    int lane = tid & 31;
    int warp = tid >> 5;
    int lr = lane >> 2, lk = lane & 3;
    int rowBase = blockIdx.x * 128;

    for (int i = tid; i < 128 * 8; i += 256) {
        int r = i >> 3, seg = (i & 7) * 8;
        int gr = rowBase + r;
        float4 v0 = make_float4(0.f,0.f,0.f,0.f), v1 = v0;
        if (gr < nrows) {
            v0 = *(const float4*)&g_hA[gr * 64 + seg];
            v1 = *(const float4*)&g_hA[gr * 64 + seg + 4];
        }
        uint32_t* dp = (uint32_t*)&sA[r * 72 + seg];
        dp[0] = pbf2(v0.x, v0.y); dp[1] = pbf2(v0.z, v0.w);
        dp[2] = pbf2(v1.x, v1.y); dp[3] = pbf2(v1.z, v1.w);
    }
    for (int i = tid; i < 64 * 8; i += 256) {
        int c = i >> 3, q = (i & 7) * 8;
        cp16(smem_u32(&sB[c * 72 + q]), &g_w2Bb[c * 64 + q]);
    }
    asm volatile("cp.async.commit_group;");
    asm volatile("cp.async.wait_group 0;");
    __syncthreads();

    int rowW = warp * 16;
    float acc[8][4];
#pragma unroll
    for (int nt = 0; nt < 8; nt++)
#pragma unroll
        for (int q = 0; q < 4; q++) acc[nt][q] = 0.f;

#pragma unroll
    for (int k0 = 0; k0 < 64; k0 += 16) {
        uint32_t a[4];
        a[0] = *(const uint32_t*)&sA[(rowW + lr) * 72 + k0 + 2 * lk];
        a[1] = *(const uint32_t*)&sA[(rowW + lr + 8) * 72 + k0 + 2 * lk];
        a[2] = *(const uint32_t*)&sA[(rowW + lr) * 72 + k0 + 8 + 2 * lk];
        a[3] = *(const uint32_t*)&sA[(rowW + lr + 8) * 72 + k0 + 8 + 2 * lk];
#pragma unroll
        for (int nt = 0; nt < 8; nt++) {
            int c = nt * 8 + lr;
            uint32_t b0 = *(const uint32_t*)&sB[c * 72 + k0 + 2 * lk];
            uint32_t b1 = *(const uint32_t*)&sB[c * 72 + k0 + 8 + 2 * lk];
            mma_bf16(acc[nt], a, b0, b1);
        }
    }

    int r0g = rowBase + rowW + lr;
    int r1g = r0g + 8;
    int bs0 = (r0g < nrows) ? __ldg(&batch[r0g]) : 0;
    int bs1 = (r1g < nrows) ? __ldg(&batch[r1g]) : 0;
    float al0 = 0.f, al1 = 0.f;
#pragma unroll
    for (int nt = 0; nt < 8; nt++) {
#pragma unroll
        for (int q = 0; q < 2; q++) {
            int c = nt * 8 + 2 * lk + q;
            float bias = __ldg(&bb1[c]) + __ldg(&bb2[c]);
            float qv = __ldg(&qw[c]);
            float x0 = acc[nt][q]     + g_vnW1[bs0 * 64 + c] + bias;
            float x1 = acc[nt][2 + q] + g_vnW1[bs1 * 64 + c] + bias;
            al0 = fmaf(fsigmoid(x0), qv, al0);
            al1 = fmaf(fsigmoid(x1), qv, al1);
        }
    }
    al0 += __shfl_xor_sync(0xffffffffu, al0, 1);
    al0 += __shfl_xor_sync(0xffffffffu, al0, 2);
    al1 += __shfl_xor_sync(0xffffffffu, al1, 1);
    al1 += __shfl_xor_sync(0xffffffffu, al1, 2);
    float qbv = __ldg(&qb[0]);
    al0 += qbv; al1 += qbv;
#pragma unroll
    for (int nt = 0; nt < 8; nt++) {
#pragma unroll
        for (int q = 0; q < 2; q++) {
            int c = nt * 8 + 2 * lk + q;
            if (r0g < nrows) atomicAdd(&g_sg[bs0 * 64 + c], al0 * g_hA[r0g * 64 + c]);
            if (r1g < nrows) atomicAdd(&g_sg[bs1 * 64 + c], al1 * g_hA[r1g * 64 + c]);
        }
    }
}

// --------------------- final accum: g_sh += g_sg @ W3b^T + b3
__global__ void __launch_bounds__(256) shb_gemm(
    const float* __restrict__ W3, const float* __restrict__ b3, int S)
{
    __shared__ float sAt[64][68];
    __shared__ float sB [64][68];
    int tid = threadIdx.x;
    int rowBase = blockIdx.x * 64;

    for (int i = tid; i < 64 * 64; i += 256) {
        int r = i >> 6, k = i & 63;
        int s = rowBase + r;
        sAt[k][r] = (s < S) ? g_sg[s * 64 + k] : 0.f;
    }
    for (int i = tid; i < 64 * 64; i += 256) {
        int j = i >> 6, k = i & 63;
        sB[k][j] = W3[j * 128 + 64 + k];
    }
    __syncthreads();

    int r0 = (tid >> 4) * 4, c0 = (tid & 15) * 4;
    float acc[4][4] = {};
#pragma unroll
    for (int k = 0; k < 64; k++) {
        float4 a = *(const float4*)&sAt[k][r0];
        float4 b = *(const float4*)&sB[k][c0];
        float av[4] = {a.x, a.y, a.z, a.w};
        float bv[4] = {b.x, b.y, b.z, b.w};
#pragma unroll
        for (int i = 0; i < 4; i++)
#pragma unroll
            for (int j = 0; j < 4; j++)
                acc[i][j] = fmaf(av[i], bv[j], acc[i][j]);
    }

    float4 bb = make_float4(b3[c0], b3[c0+1], b3[c0+2], b3[c0+3]);
#pragma unroll
    for (int i = 0; i < 4; i++) {
        int s = rowBase + r0 + i;
        if (s < S) {
            float* cp = &g_sh[s * 64 + c0];
            float4 p = *(const float4*)cp;
            *(float4*)cp = make_float4(acc[i][0] + bb.x + p.x, acc[i][1] + bb.y + p.y,
                                       acc[i][2] + bb.z + p.z, acc[i][3] + bb.w + p.w);
        }
    }
}

// ------------------------------------------------------------ BPR loss
__global__ void loss_kernel(const float* __restrict__ item_emb,
                            const int* __restrict__ pos, const int* __restrict__ neg,
                            int S)
{
    int gidx = blockIdx.x * blockDim.x + threadIdx.x;
    int s = gidx >> 5;
    if (s >= S) return;
    int lane = gidx & 31;
    int ip = pos[s], in2 = neg[s];
    float pp = 0.f, np = 0.f, rg = 0.f;
#pragma unroll
    for (int t = 0; t < 2; t++) {
        int j = lane + t * 32;
        float sv = g_sh[s * 64 + j];
        float pe = item_emb[ip * 64 + j];
        float ne = item_emb[in2 * 64 + j];
        pp = fmaf(sv, pe, pp);
        np = fmaf(sv, ne, np);
        rg += sv * sv + pe * pe + ne * ne;
    }
#pragma unroll
    for (int o = 16; o; o >>= 1) {
        pp += __shfl_xor_sync(0xffffffffu, pp, o);
        np += __shfl_xor_sync(0xffffffffu, np, o);
        rg += __shfl_xor_sync(0xffffffffu, rg, o);
    }
    if (lane == 0) {
        float x = pp - np;
        float lsm = (x > 0.f) ? log1pf(expf(-x)) : (-x + log1pf(expf(x)));
        atomicAdd(&g_acc[0], (double)lsm);
        atomicAdd(&g_acc[1], (double)rg);
    }
}

__global__ void finalize_kernel(float* out, int out_size)
{
    double loss = g_acc[0];
    double nr = g_acc[1] * 1e-5;
    float t = (float)(loss + nr), l = (float)loss, r = (float)nr;
    if (out_size > 0) out[0] = t;
    if (out_size > 1) out[1] = l;
    if (out_size > 2) out[2] = r;
    if (out_size > 3) out[3] = r;
    if (out_size > 4) out[4] = r;
}

// ---------------------------------------------------------------- host
extern "C" void kernel_launch(void* const* d_in, const int* in_sizes, int n_in,
                              void* d_out, int out_size)
{
    const float* item_emb = (const float*)d_in[0];
    const float* ggc      = (const float*)d_in[1];
    const float* W_ih     = (const float*)d_in[2];
    const float* b_ih     = (const float*)d_in[3];
    const float* W_hh     = (const float*)d_in[4];
    const float* b_hh     = (const float*)d_in[5];
    const float* W1       = (const float*)d_in[6];
    const float* b1       = (const float*)d_in[7];
    const float* W2       = (const float*)d_in[8];
    const float* b2       = (const float*)d_in[9];
    const float* qw       = (const float*)d_in[10];
    const float* qb       = (const float*)d_in[11];
    const float* W3       = (const float*)d_in[12];
    const float* b3       = (const float*)d_in[13];
    const int* node_items = (const int*)d_in[14];
    const int* edge_index = (const int*)d_in[15];
    const int* batch      = (const int*)d_in[16];
    const int* pos        = (const int*)d_in[17];
    const int* neg        = (const int*)d_in[18];

    int N = in_sizes[14];
    int E = in_sizes[15] / 2;
    int S = in_sizes[17];
    float* out = (float*)d_out;

    cudaFuncSetAttribute(gnn2,       cudaFuncAttributeMaxDynamicSharedMemorySize, GNN_SMEM);
    cudaFuncSetAttribute(w2gate_mma, cudaFuncAttributeMaxDynamicSharedMemorySize, W2_SMEM);
    cudaFuncSetAttribute(vn_mma,     cudaFuncAttributeMaxDynamicSharedMemorySize, VN_SMEM);

    const int* src = edge_index;
    const int* dst = edge_index + E;
    int initCnt = S * D;                      // 1,048,576 >= all init ranges
    if (initCnt < N) initCnt = N;

    init_all<<<(initCnt + 255) / 256, 256>>>(W_ih, W_hh, ggc, W2, batch, S, N);
    build_inedge_kernel<<<(E + 255) / 256, 256>>>(src, dst, E);

    gnn2<<<(N + 63) / 64, 256, GNN_SMEM>>>(b_ih, b_hh, N, item_emb, node_items);

    vn_mma<<<(S + 63) / 64, 256, VN_SMEM>>>(W1, W3, S);
    w2gate_mma<<<(N + 127) / 128, 256, W2_SMEM>>>(batch, b1, b2, qw, qb, N);
    shb_gemm<<<(S + 63) / 64, 256>>>(W3, b3, S);

    loss_kernel<<<(S * 32 + 255) / 256, 256>>>(item_emb, pos, neg, S);
    finalize_kernel<<<1, 1>>>(out, out_size);
}